// round 17
// baseline (speedup 1.0000x reference)
#include <cuda_runtime.h>
#include <cuda_bf16.h>
#include <cstdint>

#define NN 10000
#define NE 160000
#define FD 128
#define F8 1024

__device__ float g_phi[(size_t)NN * F8];

// ===========================================================================
// warp-level bf16 MMA (sm_80+ baseline — portable to compute_103)
// ===========================================================================
__device__ __forceinline__ void mma_bf16(float d[4],
    uint32_t a0, uint32_t a1, uint32_t a2, uint32_t a3,
    uint32_t b0, uint32_t b1)
{
    asm volatile(
        "mma.sync.aligned.m16n8k16.row.col.f32.bf16.bf16.f32 "
        "{%0,%1,%2,%3}, {%4,%5,%6,%7}, {%8,%9}, {%0,%1,%2,%3};\n"
        : "+f"(d[0]), "+f"(d[1]), "+f"(d[2]), "+f"(d[3])
        : "r"(a0), "r"(a1), "r"(a2), "r"(a3), "r"(b0), "r"(b1));
}

__device__ __forceinline__ uint32_t pack_bf16x2(float lo_val, float hi_val) {
    __nv_bfloat162 p = __floats2bfloat162_rn(lo_val, hi_val);
    return *(uint32_t*)&p;
}

__device__ __forceinline__ void red_add_v2(float* p, float a, float b) {
    asm volatile("red.global.add.v2.f32 [%0], {%1, %2};"
                 :: "l"(p), "f"(a), "f"(b) : "memory");
}

__device__ __forceinline__ void cp_async16(uint32_t dst_smem, const void* src) {
    asm volatile("cp.async.ca.shared.global [%0], [%1], 16;"
                 :: "r"(dst_smem), "l"(src) : "memory");
}
#define CP_COMMIT() asm volatile("cp.async.commit_group;" ::: "memory")
#define CP_WAIT0()  asm volatile("cp.async.wait_group 0;" ::: "memory")

// ===========================================================================
// phi = silu(s @ W1 + b1) @ W2 + b2    (unchanged — passing since R14)
// ===========================================================================
#define PHI_BM 32
#define PHI_HA    0
#define PHI_W2T   17408
#define PHI_B2S   84992
#define PHI_SMEM  89088

__global__ __launch_bounds__(256) void phi_kernel(
    const float* __restrict__ s,
    const float* __restrict__ W1, const float* __restrict__ b1,
    const float* __restrict__ W2, const float* __restrict__ b2)
{
    extern __shared__ char smc[];
    float* A = (float*)smc;
    float* B = (float*)(smc + 16384);
    float* b2s = (float*)(smc + PHI_B2S);

    const int t = threadIdx.x;
    const int row0 = blockIdx.x * PHI_BM;
    const int tx = t & 31;
    const int ty = t >> 5;
    const int lane = t & 31;
    const int wid  = t >> 5;
    const int grp  = lane >> 2;
    const int qid  = lane & 3;

    for (int i = t; i < 1024; i += 256) b2s[i] = b2[i];

    {
        const float4* s4 = (const float4*)s;
        #pragma unroll
        for (int i = 0; i < 4; i++) {
            int idx = t + 256 * i;
            int r = idx >> 5;
            float4 val = make_float4(0.f, 0.f, 0.f, 0.f);
            if (row0 + r < NN) val = s4[(size_t)(row0 + r) * 32 + (idx & 31)];
            ((float4*)A)[idx] = val;
        }
        const float4* w4 = (const float4*)W1;
        #pragma unroll
        for (int i = 0; i < 16; i++)
            ((float4*)B)[t + 256 * i] = w4[t + 256 * i];
    }
    __syncthreads();

    float acc1[4][4];
    #pragma unroll
    for (int i = 0; i < 4; i++)
        #pragma unroll
        for (int j = 0; j < 4; j++) acc1[i][j] = 0.f;

    #pragma unroll 8
    for (int k = 0; k < FD; k++) {
        float4 bv = ((float4*)B)[k * 32 + tx];
        #pragma unroll
        for (int i = 0; i < 4; i++) {
            float a = A[(ty * 4 + i) * FD + k];
            acc1[i][0] += a * bv.x; acc1[i][1] += a * bv.y;
            acc1[i][2] += a * bv.z; acc1[i][3] += a * bv.w;
        }
    }
    float4 b1v = ((const float4*)b1)[tx];
    __syncthreads();

    #pragma unroll
    for (int i = 0; i < 4; i++) {
        float h[4];
        h[0] = acc1[i][0] + b1v.x; h[1] = acc1[i][1] + b1v.y;
        h[2] = acc1[i][2] + b1v.z; h[3] = acc1[i][3] + b1v.w;
        #pragma unroll
        for (int j = 0; j < 4; j++) h[j] = h[j] / (1.f + __expf(-h[j]));

        __nv_bfloat16 hh[4];
        float         hl[4];
        #pragma unroll
        for (int j = 0; j < 4; j++) {
            hh[j] = __float2bfloat16_rn(h[j]);
            hl[j] = h[j] - __bfloat162float(hh[j]);
        }
        char* rp = smc + PHI_HA + (ty * 4 + i) * 528;
        uint2 hiw, low;
        { __nv_bfloat162 p0 = {hh[0], hh[1]}, p1 = {hh[2], hh[3]};
          hiw.x = *(uint32_t*)&p0; hiw.y = *(uint32_t*)&p1; }
        low.x = pack_bf16x2(hl[0], hl[1]);
        low.y = pack_bf16x2(hl[2], hl[3]);
        *(uint2*)(rp + 8 * tx)       = hiw;
        *(uint2*)(rp + 256 + 8 * tx) = low;
    }
    __syncthreads();

    const int mtile = wid & 1;
    const int nbase = (wid >> 1) * 32;

    for (int g = 0; g < 8; g++) {
        #pragma unroll 4
        for (int q = 0; q < 32; q++) {
            int k = 4 * q + 2 * (t >> 7);
            int n = t & 127;
            float v0 = W2[(size_t)k * 1024 + g * 128 + n];
            float v1 = W2[(size_t)(k + 1) * 1024 + g * 128 + n];
            __nv_bfloat16 h0 = __float2bfloat16_rn(v0);
            __nv_bfloat16 h1 = __float2bfloat16_rn(v1);
            float l0 = v0 - __bfloat162float(h0);
            float l1 = v1 - __bfloat162float(h1);
            char* rp = smc + PHI_W2T + n * 528;
            __nv_bfloat162 hp = {h0, h1};
            *(uint32_t*)(rp + 2 * k)       = *(uint32_t*)&hp;
            *(uint32_t*)(rp + 256 + 2 * k) = pack_bf16x2(l0, l1);
        }
        __syncthreads();

        float acc[4][4];
        #pragma unroll
        for (int nt = 0; nt < 4; nt++) {
            acc[nt][0] = 0.f; acc[nt][1] = 0.f; acc[nt][2] = 0.f; acc[nt][3] = 0.f;
        }

        #pragma unroll
        for (int ks = 0; ks < 8; ks++) {
            const char* ar  = smc + PHI_HA + (mtile * 16 + grp) * 528 + ks * 32 + qid * 4;
            const char* ar8 = ar + 8 * 528;
            uint32_t ah0 = *(const uint32_t*)(ar);
            uint32_t ah1 = *(const uint32_t*)(ar8);
            uint32_t ah2 = *(const uint32_t*)(ar + 16);
            uint32_t ah3 = *(const uint32_t*)(ar8 + 16);
            uint32_t al0 = *(const uint32_t*)(ar + 256);
            uint32_t al1 = *(const uint32_t*)(ar8 + 256);
            uint32_t al2 = *(const uint32_t*)(ar + 272);
            uint32_t al3 = *(const uint32_t*)(ar8 + 272);
            #pragma unroll
            for (int nt = 0; nt < 4; nt++) {
                const char* brp = smc + PHI_W2T + (nbase + nt * 8 + grp) * 528 + ks * 32 + qid * 4;
                uint32_t bh0 = *(const uint32_t*)(brp);
                uint32_t bh1 = *(const uint32_t*)(brp + 16);
                uint32_t bl0 = *(const uint32_t*)(brp + 256);
                uint32_t bl1 = *(const uint32_t*)(brp + 272);
                mma_bf16(acc[nt], ah0, ah1, ah2, ah3, bh0, bh1);
                mma_bf16(acc[nt], ah0, ah1, ah2, ah3, bl0, bl1);
                mma_bf16(acc[nt], al0, al1, al2, al3, bh0, bh1);
            }
        }
        __syncthreads();

        #pragma unroll
        for (int nt = 0; nt < 4; nt++) {
            int n = nbase + nt * 8 + qid * 2;
            float bb0 = b2s[g * 128 + n], bb1 = b2s[g * 128 + n + 1];
            int r = row0 + mtile * 16 + grp;
            if (r < NN) {
                float2 o = make_float2(acc[nt][0] + bb0, acc[nt][1] + bb1);
                *(float2*)&g_phi[(size_t)r * 1024 + g * 128 + n] = o;
            }
            int r2 = r + 8;
            if (r2 < NN) {
                float2 o = make_float2(acc[nt][2] + bb0, acc[nt][3] + bb1);
                *(float2*)&g_phi[(size_t)r2 * 1024 + g * 128 + n] = o;
            }
        }
    }
}

// ===========================================================================
// Edge kernel R17 — phi staged densely via cp.async, pipelined by g-half.
//   PA: cur tile phi cols [0,512)   PB: cur tile phi cols [512,1024)
//   per tile: issue cp(half1->PB); compute g0-3 (PA); STS next scalars;
//             wait+bar; issue cp(next half0->PA); compute g4-7 (PB);
//             reds; STS next rc; wait+bar.
// ===========================================================================
#define ET 16
#define NT (NE / ET)    // 10000
#define EGRID 152

#define SM_AS   0                        // WrT: 1024 rows x 144B = 147456
#define SM_BRS  147456                   // br: 4096
#define SM_T0   151552                   // tile buffer 0 (3072B)
#define SM_T1   154624                   // tile buffer 1
#define SM_PA   157696                   // phi half buffer A (16 x 2064B)
#define SM_PB   190720                   // phi half buffer B
#define TB_US   2304
#define TB_FSS  2880
#define TB_II   2944
#define TB_JJ   3008
#define PR      2064                     // phi row stride (516 words, pad 4)
#define EDGE_SMEM 223744

__global__ __launch_bounds__(512, 1) void edge_kernel(
    const float* __restrict__ re1, const float* __restrict__ re2, const float* __restrict__ re3,
    const float* __restrict__ fc1, const float* __restrict__ fc2, const float* __restrict__ fc3,
    const float* __restrict__ u1, const float* __restrict__ u2, const float* __restrict__ u3,
    const int* __restrict__ eidx,
    const float* __restrict__ Wr, const float* __restrict__ br,
    const float* __restrict__ v,
    float* __restrict__ out_s, float* __restrict__ out_v)
{
    extern __shared__ char smc[];
    const int t    = threadIdx.x;
    const int lane = t & 31;
    const int wid  = t >> 5;
    const int grp  = lane >> 2;
    const int qid  = lane & 3;
    const int f0   = wid * 8 + qid * 2;

    float* brs = (float*)(smc + SM_BRS);
    const uint32_t pa_u32 = (uint32_t)__cvta_generic_to_shared(smc + SM_PA) + wid * PR;
    const uint32_t pb_u32 = (uint32_t)__cvta_generic_to_shared(smc + SM_PB) + wid * PR;

    // ---- stage WrT hi/lo into As, once per block ----
    #pragma unroll 4
    for (int i = 0; i < 64; i++) {
        int idx = t + 512 * i;
        int k   = idx >> 10;
        int row = idx & 1023;
        float val = Wr[k * 1024 + row];
        __nv_bfloat16 hi = __float2bfloat16_rn(val);
        float lo = val - __bfloat162float(hi);
        char* rp = smc + SM_AS + row * 144;
        *(__nv_bfloat16*)(rp + 2 * k)      = hi;
        *(__nv_bfloat16*)(rp + 64 + 2 * k) = __float2bfloat16_rn(lo);
    }
    for (int i = t; i < 1024; i += 512) brs[i] = br[i];

    // ---- prologue: stage first tile scalars+rc into T0 ----
    {
        char* bnx = smc + SM_T0;
        int e0n = blockIdx.x * ET;
        {
            int e = t >> 5, k = t & 31;
            int ge = e0n + e;
            float val = re1[ge * 32 + k] * fc1[ge]
                      + re2[ge * 32 + k] * fc2[ge]
                      + re3[ge * 32 + k] * fc3[ge];
            __nv_bfloat16 hi = __float2bfloat16_rn(val);
            float lo = val - __bfloat162float(hi);
            char* rp = bnx + e * 144;
            *(__nv_bfloat16*)(rp + 2 * k)      = hi;
            *(__nv_bfloat16*)(rp + 64 + 2 * k) = __float2bfloat16_rn(lo);
        }
        if (t < ET * 9) {
            int e = t / 9, c = t % 9;
            int ge = e0n + e;
            ((float*)(bnx + TB_US))[t] =
                  (c < 3) ? u1[ge * 3 + c]
                : (c < 6) ? u2[ge * 3 + (c - 3)]
                          : u3[ge * 3 + (c - 6)];
        }
        if (t < ET) {
            int ge = e0n + t;
            ((float*)(bnx + TB_FSS))[t] = fc1[ge] + fc2[ge] + fc3[ge];
            ((int*)(bnx + TB_II))[t] = eidx[ge];
            ((int*)(bnx + TB_JJ))[t] = eidx[NE + ge];
        }
    }
    __syncthreads();

    // ---- prologue: stage tile0 phi half0 -> PA ----
    {
        int nj = ((const int*)(smc + SM_T0 + TB_JJ))[wid];
        const char* src = (const char*)(g_phi + (size_t)nj * 1024);
        #pragma unroll
        for (int r = 0; r < 4; r++)
            cp_async16(pa_u32 + r * 512 + lane * 16, src + r * 512 + lane * 16);
        CP_COMMIT(); CP_WAIT0();
    }
    __syncthreads();

    int iter = 0;
    for (int tile = blockIdx.x; tile < NT; tile += EGRID, iter++) {
        char* buf = smc + ((iter & 1) ? SM_T1 : SM_T0);
        char* bnx = smc + ((iter & 1) ? SM_T0 : SM_T1);
        const int tnext = tile + EGRID;
        const bool do_next = tnext < NT;

        // ---- A) prefetch LDGs for next tile ----
        float p_r0 = 0.f, p_r1 = 0.f, p_r2 = 0.f;
        float p_f0 = 0.f, p_f1 = 0.f, p_f2 = 0.f;
        float p_u = 0.f, p_g1 = 0.f, p_g2 = 0.f, p_g3 = 0.f;
        int   p_ii = 0, p_jj = 0;
        if (do_next) {
            int e0n = tnext * ET;
            {
                int e = t >> 5, k = t & 31;
                int ge = e0n + e;
                p_f0 = fc1[ge]; p_f1 = fc2[ge]; p_f2 = fc3[ge];
                p_r0 = re1[ge * 32 + k]; p_r1 = re2[ge * 32 + k]; p_r2 = re3[ge * 32 + k];
            }
            if (t < ET * 9) {
                int e = t / 9, c = t % 9;
                int ge = e0n + e;
                p_u = (c < 3) ? u1[ge * 3 + c]
                    : (c < 6) ? u2[ge * 3 + (c - 3)]
                              : u3[ge * 3 + (c - 6)];
            }
            if (t < ET) {
                int ge = e0n + t;
                p_g1 = fc1[ge]; p_g2 = fc2[ge]; p_g3 = fc3[ge];
                p_ii = eidx[ge]; p_jj = eidx[NE + ge];
            }
        }

        // ---- issue cp.async: cur half1 -> PB ----
        {
            int nj = ((const int*)(buf + TB_JJ))[wid];
            const char* src = (const char*)(g_phi + (size_t)nj * 1024 + 512);
            #pragma unroll
            for (int r = 0; r < 4; r++)
                cp_async16(pb_u32 + r * 512 + lane * 16, src + r * 512 + lane * 16);
            CP_COMMIT();
        }

        // ---- tile-local data ----
        const float* us  = (const float*)(buf + TB_US);
        const float* fss = (const float*)(buf + TB_FSS);
        const int*   ii  = (const int*)(buf + TB_II);
        const int*   jj  = (const int*)(buf + TB_JJ);

        const char* ar  = buf + grp * 144 + qid * 4;
        const char* ar8 = ar + 8 * 144;
        const uint32_t ah0 = *(const uint32_t*)(ar);
        const uint32_t ah1 = *(const uint32_t*)(ar8);
        const uint32_t ah2 = *(const uint32_t*)(ar + 16);
        const uint32_t ah3 = *(const uint32_t*)(ar8 + 16);
        const uint32_t ah4 = *(const uint32_t*)(ar + 32);
        const uint32_t ah5 = *(const uint32_t*)(ar8 + 32);
        const uint32_t ah6 = *(const uint32_t*)(ar + 48);
        const uint32_t ah7 = *(const uint32_t*)(ar8 + 48);
        const uint32_t al0 = *(const uint32_t*)(ar + 64);
        const uint32_t al1 = *(const uint32_t*)(ar8 + 64);
        const uint32_t al2 = *(const uint32_t*)(ar + 80);
        const uint32_t al3 = *(const uint32_t*)(ar8 + 80);
        const uint32_t al4 = *(const uint32_t*)(ar + 96);
        const uint32_t al5 = *(const uint32_t*)(ar8 + 96);
        const uint32_t al6 = *(const uint32_t*)(ar + 112);
        const uint32_t al7 = *(const uint32_t*)(ar8 + 112);

        const int e0 = grp, e1 = grp + 8;
        const int nj0 = jj[e0], nj1 = jj[e1];
        const int ni0 = ii[e0], ni1 = ii[e1];
        const float fs0 = fss[e0], fs1 = fss[e1];

        const float* vp0 = v + (size_t)nj0 * (3 * FD) + f0;
        const float* vp1 = v + (size_t)nj1 * (3 * FD) + f0;
        const float2 vj00 = *(const float2*)(vp0);
        const float2 vj01 = *(const float2*)(vp0 + FD);
        const float2 vj02 = *(const float2*)(vp0 + 2 * FD);
        const float2 vj10 = *(const float2*)(vp1);
        const float2 vj11 = *(const float2*)(vp1 + FD);
        const float2 vj12 = *(const float2*)(vp1 + 2 * FD);

        float uA[9], uB[9];
        #pragma unroll
        for (int c = 0; c < 9; c++) { uA[c] = us[e0 * 9 + c]; uB[c] = us[e1 * 9 + c]; }

        float ds00 = 0.f, ds01 = 0.f, ds10 = 0.f, ds11 = 0.f;
        float dv000 = 0.f, dv001 = 0.f, dv010 = 0.f, dv011 = 0.f, dv020 = 0.f, dv021 = 0.f;
        float dv100 = 0.f, dv101 = 0.f, dv110 = 0.f, dv111 = 0.f, dv120 = 0.f, dv121 = 0.f;

        // fold macro: g resolved at compile time after unroll
        #define EDGE_FOLD(G, X00, X01, X10, X11)                                  \
            if ((G) == 0) {                                                       \
                ds00 += (X00); ds01 += (X01); ds10 += (X10); ds11 += (X11);       \
            } else if ((G) == 1) {                                                \
                dv000 += vj00.x * (X00); dv001 += vj00.y * (X01);                 \
                dv010 += vj01.x * (X00); dv011 += vj01.y * (X01);                 \
                dv020 += vj02.x * (X00); dv021 += vj02.y * (X01);                 \
                dv100 += vj10.x * (X10); dv101 += vj10.y * (X11);                 \
                dv110 += vj11.x * (X10); dv111 += vj11.y * (X11);                 \
                dv120 += vj12.x * (X10); dv121 += vj12.y * (X11);                 \
            } else if ((G) <= 4) {                                                \
                const int k3 = ((G) - 2) * 3;                                     \
                dv000 += uA[k3] * (X00);     dv001 += uA[k3] * (X01);             \
                dv010 += uA[k3 + 1] * (X00); dv011 += uA[k3 + 1] * (X01);         \
                dv020 += uA[k3 + 2] * (X00); dv021 += uA[k3 + 2] * (X01);         \
                dv100 += uB[k3] * (X10);     dv101 += uB[k3] * (X11);             \
                dv110 += uB[k3 + 1] * (X10); dv111 += uB[k3 + 1] * (X11);         \
                dv120 += uB[k3 + 2] * (X10); dv121 += uB[k3 + 2] * (X11);         \
            } else {                                                              \
                const int k3 = ((G) - 5) * 3;                                     \
                const float ax = uA[k3], ay = uA[k3 + 1], az = uA[k3 + 2];        \
                dv000 += (vj01.x * az - vj02.x * ay) * (X00);                     \
                dv001 += (vj01.y * az - vj02.y * ay) * (X01);                     \
                dv010 += (vj02.x * ax - vj00.x * az) * (X00);                     \
                dv011 += (vj02.y * ax - vj00.y * az) * (X01);                     \
                dv020 += (vj00.x * ay - vj01.x * ax) * (X00);                     \
                dv021 += (vj00.y * ay - vj01.y * ax) * (X01);                     \
                const float bx = uB[k3], by = uB[k3 + 1], bz = uB[k3 + 2];        \
                dv100 += (vj11.x * bz - vj12.x * by) * (X10);                     \
                dv101 += (vj11.y * bz - vj12.y * by) * (X11);                     \
                dv110 += (vj12.x * bx - vj10.x * bz) * (X10);                     \
                dv111 += (vj12.y * bx - vj10.y * bz) * (X11);                     \
                dv120 += (vj10.x * by - vj11.x * bx) * (X10);                     \
                dv121 += (vj10.y * by - vj11.y * bx) * (X11);                     \
            }

        #define EDGE_MMA_G(G, PBASE, OFF)                                         \
        {                                                                         \
            const char* brp = smc + SM_AS + ((G) * 128 + wid * 8 + grp) * 144 + qid * 4; \
            const uint32_t bh0 = *(const uint32_t*)(brp);                         \
            const uint32_t bh1 = *(const uint32_t*)(brp + 16);                    \
            const uint32_t bh2 = *(const uint32_t*)(brp + 32);                    \
            const uint32_t bh3 = *(const uint32_t*)(brp + 48);                    \
            const uint32_t bl0 = *(const uint32_t*)(brp + 64);                    \
            const uint32_t bl1 = *(const uint32_t*)(brp + 80);                    \
            const uint32_t bl2 = *(const uint32_t*)(brp + 96);                    \
            const uint32_t bl3 = *(const uint32_t*)(brp + 112);                   \
            float acc[4] = {0.f, 0.f, 0.f, 0.f};                                  \
            mma_bf16(acc, ah0, ah1, ah2, ah3, bh0, bh1);                          \
            mma_bf16(acc, ah4, ah5, ah6, ah7, bh2, bh3);                          \
            mma_bf16(acc, ah0, ah1, ah2, ah3, bl0, bl1);                          \
            mma_bf16(acc, ah4, ah5, ah6, ah7, bl2, bl3);                          \
            mma_bf16(acc, al0, al1, al2, al3, bh0, bh1);                          \
            mma_bf16(acc, al4, al5, al6, al7, bh2, bh3);                          \
            const float2 brf = *(const float2*)&brs[(G) * 128 + f0];              \
            const int col = ((G) * 128 + f0 - (OFF)) * 4;                         \
            const float2 ph0 = *(const float2*)((PBASE) + e0 * PR + col);         \
            const float2 ph1 = *(const float2*)((PBASE) + e1 * PR + col);         \
            const float x00 = ph0.x * (acc[0] + brf.x * fs0);                     \
            const float x01 = ph0.y * (acc[1] + brf.y * fs0);                     \
            const float x10 = ph1.x * (acc[2] + brf.x * fs1);                     \
            const float x11 = ph1.y * (acc[3] + brf.y * fs1);                     \
            EDGE_FOLD(G, x00, x01, x10, x11)                                      \
        }

        // ---- compute g = 0..3 from PA ----
        {
            const char* pA = smc + SM_PA;
            #pragma unroll
            for (int g = 0; g < 4; g++) EDGE_MMA_G(g, pA, 0)
        }

        // ---- STS next scalars (so next-half0 cp can read jj) ----
        if (do_next) {
            if (t < ET * 9) ((float*)(bnx + TB_US))[t] = p_u;
            if (t < ET) {
                ((float*)(bnx + TB_FSS))[t] = p_g1 + p_g2 + p_g3;
                ((int*)(bnx + TB_II))[t] = p_ii;
                ((int*)(bnx + TB_JJ))[t] = p_jj;
            }
        }

        CP_WAIT0();
        __syncthreads();   // PB ready; bnx scalars visible

        // ---- issue cp.async: next tile half0 -> PA ----
        if (do_next) {
            int nj = ((const int*)(bnx + TB_JJ))[wid];
            const char* src = (const char*)(g_phi + (size_t)nj * 1024);
            #pragma unroll
            for (int r = 0; r < 4; r++)
                cp_async16(pa_u32 + r * 512 + lane * 16, src + r * 512 + lane * 16);
            CP_COMMIT();
        }

        // ---- compute g = 4..7 from PB ----
        {
            const char* pB = smc + SM_PB;
            #pragma unroll
            for (int g = 4; g < 8; g++) EDGE_MMA_G(g, pB, 512)
        }

        // ---- final scatter: 8 vector reds ----
        {
            red_add_v2(out_s + (size_t)ni0 * FD + f0, ds00, ds01);
            float* ov0 = out_v + (size_t)ni0 * (3 * FD) + f0;
            red_add_v2(ov0,          dv000, dv001);
            red_add_v2(ov0 + FD,     dv010, dv011);
            red_add_v2(ov0 + 2 * FD, dv020, dv021);

            red_add_v2(out_s + (size_t)ni1 * FD + f0, ds10, ds11);
            float* ov1 = out_v + (size_t)ni1 * (3 * FD) + f0;
            red_add_v2(ov1,          dv100, dv101);
            red_add_v2(ov1 + FD,     dv110, dv111);
            red_add_v2(ov1 + 2 * FD, dv120, dv121);
        }

        // ---- STS next rc ----
        if (do_next) {
            int e = t >> 5, k = t & 31;
            float val = p_r0 * p_f0 + p_r1 * p_f1 + p_r2 * p_f2;
            __nv_bfloat16 hi = __float2bfloat16_rn(val);
            float lo = val - __bfloat162float(hi);
            char* rp = bnx + e * 144;
            *(__nv_bfloat16*)(rp + 2 * k)      = hi;
            *(__nv_bfloat16*)(rp + 64 + 2 * k) = __float2bfloat16_rn(lo);
        }

        CP_WAIT0();
        __syncthreads();   // PA (next half0) ready; bnx rc visible
    }
}

// ===========================================================================
extern "C" void kernel_launch(void* const* d_in, const int* in_sizes, int n_in,
                              void* d_out, int out_size)
{
    const float* s    = (const float*)d_in[0];
    const float* v    = (const float*)d_in[1];
    const float* re1  = (const float*)d_in[2];
    const float* re2  = (const float*)d_in[3];
    const float* re3  = (const float*)d_in[4];
    const float* fc1  = (const float*)d_in[5];
    const float* fc2  = (const float*)d_in[6];
    const float* fc3  = (const float*)d_in[7];
    const float* u1   = (const float*)d_in[8];
    const float* u2   = (const float*)d_in[9];
    const float* u3   = (const float*)d_in[10];
    const int*   eidx = (const int*)d_in[11];
    const float* W1   = (const float*)d_in[12];
    const float* b1   = (const float*)d_in[13];
    const float* W2   = (const float*)d_in[14];
    const float* b2   = (const float*)d_in[15];
    const float* Wr   = (const float*)d_in[16];
    const float* br   = (const float*)d_in[17];

    float* out_s = (float*)d_out;
    float* out_v = out_s + (size_t)NN * FD;

    cudaFuncSetAttribute(phi_kernel,  cudaFuncAttributeMaxDynamicSharedMemorySize, PHI_SMEM);
    cudaFuncSetAttribute(edge_kernel, cudaFuncAttributeMaxDynamicSharedMemorySize, EDGE_SMEM);

    cudaMemcpyAsync(out_s, s, (size_t)NN * FD * sizeof(float),     cudaMemcpyDeviceToDevice, 0);
    cudaMemcpyAsync(out_v, v, (size_t)NN * 3 * FD * sizeof(float), cudaMemcpyDeviceToDevice, 0);

    phi_kernel<<<(NN + PHI_BM - 1) / PHI_BM, 256, PHI_SMEM>>>(s, W1, b1, W2, b2);

    edge_kernel<<<EGRID, 512, EDGE_SMEM>>>(re1, re2, re3, fc1, fc2, fc3,
                                           u1, u2, u3, eidx, Wr, br, v,
                                           out_s, out_v);
}